// round 1
// baseline (speedup 1.0000x reference)
#include <cuda_runtime.h>

#define NTYPES 20
#define LMAXC  13
#define DV     64

__constant__ int c_res_len[NTYPES] = {3,4,5,5,6,6,6,7,7,7,7,7,8,8,8,9,10,10,11,13};

__device__ int g_starts[4096];

// ---------------------------------------------------------------------------
// Kernel 0: exclusive scan of residue lengths -> starts
// ---------------------------------------------------------------------------
__global__ void scan_starts(const int* __restrict__ seq, int nres) {
    __shared__ int sa[2112];
    __shared__ int sb[2112];
    const int tid = threadIdx.x;
    for (int j = tid; j < nres; j += blockDim.x) sa[j] = c_res_len[seq[j]];
    __syncthreads();
    int* a = sa;
    int* b = sb;
    for (int off = 1; off < nres; off <<= 1) {
        for (int j = tid; j < nres; j += blockDim.x)
            b[j] = a[j] + ((j >= off) ? a[j - off] : 0);
        __syncthreads();
        int* t = a; a = b; b = t;
    }
    for (int j = tid; j < nres; j += blockDim.x)
        g_starts[j] = (j == 0) ? 0 : a[j - 1];
}

// ---------------------------------------------------------------------------
// Main kernel: one block per residue, loop over batches.
// smemW rows: pair p in [0,(L+1)*64); row = 13 floats. p = m*64+v (m==L -> amn).
// ---------------------------------------------------------------------------
#define PACK_DUP(dst, w) \
    asm("mov.b64 %0, {%1, %2};" : "=l"(dst) : "r"(__float_as_uint(w)), "r"(__float_as_uint(w)))
#define FMA2(acc, a, b) \
    asm("fma.rn.f32x2 %0, %1, %2, %3;" : "=l"(acc) : "l"(a), "l"(b), "l"(acc))
#define UNPACK2(lo, hi, src) \
    asm("mov.b64 {%0, %1}, %2;" : "=r"(lo), "=r"(hi) : "l"(src))

template <int L>
__device__ __forceinline__ void residue_work(
    int i, int start, int B, int nres, int atoms, int tid,
    const float* __restrict__ pos_atm, const float* __restrict__ pos_amn,
    const float* __restrict__ smemW, float* __restrict__ dbuf,
    float* __restrict__ out_atm, float* __restrict__ out_amn)
{
    const int nPairs = (L + 1) * DV;

    // stage diff for batch 0 into dbuf[0]
    if (tid < 3 * L) {
        const int l = tid / 3, d = tid - l * 3;
        dbuf[l * 4 + d] = pos_atm[(start + l) * 3 + d] - pos_amn[i * 3 + d];
    }
    __syncthreads();   // also covers the weight-staging done by the caller

    for (int b = 0; b < B; ++b) {
        const float* cur = dbuf + (b & 1) * 64;

        // cache diff in registers, (d0,d1) packed + d2 scalar
        unsigned long long dif01[L];
        float dif2[L];
#pragma unroll
        for (int l = 0; l < L; ++l) {
            dif01[l] = *reinterpret_cast<const unsigned long long*>(cur + l * 4);
            dif2[l]  = cur[l * 4 + 2];
        }

        // stage next batch's diff into the other buffer
        if (b + 1 < B && tid < 3 * L) {
            const int l = tid / 3, d = tid - l * 3;
            dbuf[((b + 1) & 1) * 64 + l * 4 + d] =
                pos_atm[((b + 1) * atoms + start + l) * 3 + d] -
                pos_amn[((b + 1) * nres  + i) * 3 + d];
        }
        __syncthreads();

        for (int p = tid; p < nPairs; p += 256) {
            const float* wr = smemW + p * LMAXC;   // stride 13: conflict-free
            unsigned long long a01 = 0ull;
            float a2 = 0.0f;
#pragma unroll
            for (int l = 0; l < L; ++l) {
                const float w = wr[l];
                unsigned long long ww;
                PACK_DUP(ww, w);
                FMA2(a01, ww, dif01[l]);
                a2 = fmaf(w, dif2[l], a2);
            }
            const int m = p >> 6;
            const int v = p & 63;
            float* o = (m < L)
                ? out_atm + ((size_t)((b * atoms + start + m) * DV + v)) * 3
                : out_amn + ((size_t)((b * nres  + i) * DV + v)) * 3;
            unsigned int lo, hi;
            UNPACK2(lo, hi, a01);
            o[0] = __uint_as_float(lo);
            o[1] = __uint_as_float(hi);
            o[2] = a2;
        }
        // no trailing sync needed: buffer (b&1) is only rewritten in iter b+1
        // by threads that already passed this iteration's __syncthreads()
    }
}

__global__ __launch_bounds__(256) void posmix_kernel(
    const float* __restrict__ pos_atm, const float* __restrict__ pos_amn,
    const float* __restrict__ W_amn,  const float* __restrict__ W_atm,
    const int*   __restrict__ seq,
    int B, int nres, int atoms, float* __restrict__ out)
{
    __shared__ float smemW[(LMAXC + 1) * DV * LMAXC];  // 896*13 floats = 46.6 KB
    __shared__ float dbuf[128];                        // 2 x (13*4) diff buffers

    const int i   = blockIdx.x;
    const int tid = threadIdx.x;
    const int t   = seq[i];
    const int L   = c_res_len[t];
    const int start = g_starts[i];

    // verbatim coalesced copy: W_atm[t][:L] then W_amn[t] appended
    const float* gw = W_atm + (size_t)t * LMAXC * DV * LMAXC;
    const int nAtm = L * DV * LMAXC;
    for (int j = tid; j < nAtm; j += 256) smemW[j] = gw[j];
    const float* ga = W_amn + (size_t)t * DV * LMAXC;
    for (int j = tid; j < DV * LMAXC; j += 256) smemW[nAtm + j] = ga[j];
    // visibility guaranteed by the first __syncthreads inside residue_work

    float* out_atm = out;
    float* out_amn = out + (size_t)B * atoms * DV * 3;

    switch (L) {
        case  3: residue_work< 3>(i, start, B, nres, atoms, tid, pos_atm, pos_amn, smemW, dbuf, out_atm, out_amn); break;
        case  4: residue_work< 4>(i, start, B, nres, atoms, tid, pos_atm, pos_amn, smemW, dbuf, out_atm, out_amn); break;
        case  5: residue_work< 5>(i, start, B, nres, atoms, tid, pos_atm, pos_amn, smemW, dbuf, out_atm, out_amn); break;
        case  6: residue_work< 6>(i, start, B, nres, atoms, tid, pos_atm, pos_amn, smemW, dbuf, out_atm, out_amn); break;
        case  7: residue_work< 7>(i, start, B, nres, atoms, tid, pos_atm, pos_amn, smemW, dbuf, out_atm, out_amn); break;
        case  8: residue_work< 8>(i, start, B, nres, atoms, tid, pos_atm, pos_amn, smemW, dbuf, out_atm, out_amn); break;
        case  9: residue_work< 9>(i, start, B, nres, atoms, tid, pos_atm, pos_amn, smemW, dbuf, out_atm, out_amn); break;
        case 10: residue_work<10>(i, start, B, nres, atoms, tid, pos_atm, pos_amn, smemW, dbuf, out_atm, out_amn); break;
        case 11: residue_work<11>(i, start, B, nres, atoms, tid, pos_atm, pos_amn, smemW, dbuf, out_atm, out_amn); break;
        case 12: residue_work<12>(i, start, B, nres, atoms, tid, pos_atm, pos_amn, smemW, dbuf, out_atm, out_amn); break;
        default: residue_work<13>(i, start, B, nres, atoms, tid, pos_atm, pos_amn, smemW, dbuf, out_atm, out_amn); break;
    }
}

// ---------------------------------------------------------------------------
extern "C" void kernel_launch(void* const* d_in, const int* in_sizes, int n_in,
                              void* d_out, int out_size) {
    const float* pos_atm = (const float*)d_in[0];
    const float* pos_amn = (const float*)d_in[1];
    const float* W_amn   = (const float*)d_in[2];
    const float* W_atm   = (const float*)d_in[3];
    const int*   seq     = (const int*)d_in[4];

    const int nres  = in_sizes[4];
    const int B     = in_sizes[1] / (nres * 3);
    const int atoms = in_sizes[0] / (B * 3);

    scan_starts<<<1, 1024>>>(seq, nres);
    posmix_kernel<<<nres, 256>>>(pos_atm, pos_amn, W_amn, W_atm, seq,
                                 B, nres, atoms, (float*)d_out);
}